// round 1
// baseline (speedup 1.0000x reference)
#include <cuda_runtime.h>
#include <math.h>

#define BMAX 65536
#define CH 12
#define LRAW 63
#define FLEN 7
#define VLEN 57
#define FIN 168
#define FGH 35
#define EN1 16
#define EN2 32
#define KW 6
#define L1 18
#define L2 5
#define Y1N (EN1 * L1)   // 288
#define Y2N (EN2 * L2)   // 160
#define DEH 10
#define DEOUT 50

// global scratch (allocation-free: __device__ globals)
__device__ float g_y1[(size_t)BMAX * Y1N];   // conv1 pre-activation
__device__ float g_y2[(size_t)BMAX * Y2N];   // conv2 pre-activation
__device__ float g_stats[96];                // [0:16) sum1 [16:32) sq1 [32:64) sum2 [64:96) sq2

__global__ void zero_stats_kernel() {
    if (threadIdx.x < 96) g_stats[threadIdx.x] = 0.0f;
}

// ---------------- K1: filter-gen + adaptive filter + conv1 + BN1 partials ----
// dynamic shared layout (floats):
//   [0,5880)        fg_w1 transposed [168][35]
//   [5880,5916)     fg_b1 (35, padded)
//   [5916,6164)     fg_w2 (245, padded)
//   [6164,6172)     fg_b2 (7, padded)
//   [6172,7340)     enc_w1 padded rows [16][73]
//   [7340,7356)     enc_b1
//   [7356, +w*1776) per-warp scratch:
//       sRaw[756] | sH1[36] | sFilt[8] | sEeg[684](+4 pad) | sY1[288]
#define K1_WPB 8
#define K1_WSCR 1776
#define K1_SMEMF (7356 + K1_WPB * K1_WSCR)

__global__ void __launch_bounds__(K1_WPB * 32) k1_kernel(
    const float* __restrict__ raw, const float* __restrict__ eegf,
    const float* __restrict__ fg_w1, const float* __restrict__ fg_b1,
    const float* __restrict__ fg_w2, const float* __restrict__ fg_b2,
    const float* __restrict__ enc_w1, const float* __restrict__ enc_b1,
    int bsz)
{
    extern __shared__ float sm[];
    float* s_w1T = sm;            // [i*35 + j]
    float* s_b1  = sm + 5880;
    float* s_w2  = sm + 5916;     // [j*35 + i]
    float* s_b2  = sm + 6164;
    float* s_cw  = sm + 6172;     // [o*73 + c*6 + k]
    float* s_cb  = sm + 7340;

    const int tid = threadIdx.x;
    for (int idx = tid; idx < FGH * FIN; idx += blockDim.x) {
        int j = idx / FIN, i = idx - j * FIN;
        s_w1T[i * FGH + j] = fg_w1[idx];
    }
    if (tid < FGH)  s_b1[tid] = fg_b1[tid];
    for (int idx = tid; idx < FLEN * FGH; idx += blockDim.x) s_w2[idx] = fg_w2[idx];
    if (tid < FLEN) s_b2[tid] = fg_b2[tid];
    for (int idx = tid; idx < EN1 * CH * KW; idx += blockDim.x) {
        int o = idx / (CH * KW), r = idx - o * (CH * KW);
        s_cw[o * 73 + r] = enc_w1[idx];
    }
    if (tid < EN1) s_cb[tid] = enc_b1[tid];
    __syncthreads();

    const int lane = tid & 31;
    const int wpb  = blockDim.x >> 5;
    const int gw   = blockIdx.x * wpb + (tid >> 5);
    const int nw   = gridDim.x * wpb;

    float* sw    = sm + 7356 + (tid >> 5) * K1_WSCR;
    float* sRaw  = sw;            // 756 (eegf uses first 168)
    float* sH1   = sw + 756;      // 36
    float* sFilt = sw + 792;      // 8
    float* sEeg  = sw + 800;      // 684
    float* sY1   = sw + 1488;     // 288

    float bnS = 0.0f, bnQ = 0.0f;
    const int o  = lane >> 1;          // conv1 out channel (0..15)
    const int tb = (lane & 1) * 9;     // conv1 t base (0 or 9)

    for (int b = gw; b < bsz; b += nw) {
        // ---- filter generator ----
        const float* ef = eegf + (size_t)b * FIN;
        for (int i = lane; i < FIN; i += 32) sRaw[i] = ef[i];
        __syncwarp();
        for (int j = lane; j < FGH; j += 32) {
            float acc = s_b1[j];
            #pragma unroll 8
            for (int i = 0; i < FIN; i++)
                acc = fmaf(sRaw[i], s_w1T[i * FGH + j], acc);
            sH1[j] = tanhf(acc);
        }
        __syncwarp();
        if (lane < FLEN) {
            float acc = s_b2[lane];
            #pragma unroll
            for (int i = 0; i < FGH; i++)
                acc = fmaf(sH1[i], s_w2[lane * FGH + i], acc);
            sFilt[lane] = tanhf(acc);
        }
        __syncwarp();
        const float f0 = sFilt[0], f1 = sFilt[1], f2 = sFilt[2], f3 = sFilt[3],
                    f4 = sFilt[4], f5 = sFilt[5], f6 = sFilt[6];

        // ---- load raw, adaptive 7-tap valid correlation ----
        const float* rp = raw + (size_t)b * (CH * LRAW);
        for (int i = lane; i < CH * LRAW; i += 32) sRaw[i] = rp[i];
        __syncwarp();
        for (int idx = lane; idx < CH * VLEN; idx += 32) {
            int c = idx / VLEN, t = idx - c * VLEN;
            const float* r = sRaw + c * LRAW + t;
            float a = r[0] * f0;
            a = fmaf(r[1], f1, a); a = fmaf(r[2], f2, a);
            a = fmaf(r[3], f3, a); a = fmaf(r[4], f4, a);
            a = fmaf(r[5], f5, a); a = fmaf(r[6], f6, a);
            sEeg[idx] = a;
        }
        __syncwarp();

        // ---- conv1: each lane computes 9 t-positions of one channel ----
        float acc[9];
        #pragma unroll
        for (int i = 0; i < 9; i++) acc[i] = s_cb[o];
        #pragma unroll
        for (int c = 0; c < CH; c++) {
            const float* w = s_cw + o * 73 + c * KW;
            const float w0 = w[0], w1 = w[1], w2 = w[2], w3 = w[3], w4 = w[4], w5 = w[5];
            const float* e = sEeg + c * VLEN + 3 * tb;
            float e0 = e[0], e1 = e[1], e2 = e[2], e3 = e[3], e4 = e[4], e5 = e[5];
            #pragma unroll
            for (int i = 0; i < 9; i++) {
                float a = acc[i];
                a = fmaf(e0, w0, a); a = fmaf(e1, w1, a); a = fmaf(e2, w2, a);
                a = fmaf(e3, w3, a); a = fmaf(e4, w4, a); a = fmaf(e5, w5, a);
                acc[i] = a;
                if (i < 8) {
                    e0 = e3; e1 = e4; e2 = e5;
                    e3 = e[3 * i + 6]; e4 = e[3 * i + 7]; e5 = e[3 * i + 8];
                }
            }
        }
        #pragma unroll
        for (int i = 0; i < 9; i++) sY1[o * L1 + tb + i] = acc[i];
        __syncwarp();

        // coalesced store of y1 pre-activation
        float* gy = g_y1 + (size_t)b * Y1N;
        for (int i = lane; i < Y1N; i += 32) gy[i] = sY1[i];

        // BN1 partials: lane < 16 owns channel = lane
        if (lane < EN1) {
            #pragma unroll
            for (int t = 0; t < L1; t++) {
                float v = sY1[lane * L1 + t];
                bnS += v;
                bnQ = fmaf(v, v, bnQ);
            }
        }
        __syncwarp();
    }
    if (lane < EN1) {
        atomicAdd(&g_stats[lane], bnS);
        atomicAdd(&g_stats[EN1 + lane], bnQ);
    }
}

// ---------------- K2: BN1+tanh, conv2, BN2 partials --------------------------
#define K2_WPB 8
__global__ void __launch_bounds__(K2_WPB * 32) k2_kernel(
    const float* __restrict__ enc_w2, const float* __restrict__ enc_b2,
    const float* __restrict__ bn1_g, const float* __restrict__ bn1_b,
    int bsz)
{
    __shared__ float s_w[EN2 * 97];          // padded rows [o*97 + c*6 + k]
    __shared__ float s_b[EN2];
    __shared__ float s_sc[EN1], s_sh[EN1];
    __shared__ float s_buf[K2_WPB][448];     // per warp: sH[288] | sY[160]

    const int tid = threadIdx.x;
    for (int idx = tid; idx < EN2 * EN1 * KW; idx += blockDim.x) {
        int o = idx / (EN1 * KW), r = idx - o * (EN1 * KW);
        s_w[o * 97 + r] = enc_w2[idx];
    }
    if (tid < EN2) s_b[tid] = enc_b2[tid];
    if (tid < EN1) {
        float inv = 1.0f / ((float)bsz * (float)L1);
        float m = g_stats[tid] * inv;
        float v = g_stats[EN1 + tid] * inv - m * m;
        float r = rsqrtf(v + 1e-5f);
        float sc = bn1_g[tid] * r;
        s_sc[tid] = sc;
        s_sh[tid] = bn1_b[tid] - m * sc;
    }
    __syncthreads();

    const int lane = tid & 31;
    const int w    = tid >> 5;
    const int wpb  = blockDim.x >> 5;
    const int gw   = blockIdx.x * wpb + w;
    const int nw   = gridDim.x * wpb;
    float* sH = s_buf[w];
    float* sY = s_buf[w] + Y1N;

    float bnS = 0.0f, bnQ = 0.0f;
    const int o = lane;   // conv2 out channel 0..31

    for (int b = gw; b < bsz; b += nw) {
        const float* gy = g_y1 + (size_t)b * Y1N;
        for (int i = lane; i < Y1N; i += 32) {
            int c = i / L1;
            sH[i] = tanhf(fmaf(gy[i], s_sc[c], s_sh[c]));
        }
        __syncwarp();

        float acc[L2];
        #pragma unroll
        for (int t = 0; t < L2; t++) acc[t] = s_b[o];
        #pragma unroll
        for (int c = 0; c < EN1; c++) {
            const float* wp = s_w + o * 97 + c * KW;
            const float* h  = sH + c * L1;
            float hh[L1];
            #pragma unroll
            for (int x = 0; x < L1; x++) hh[x] = h[x];
            #pragma unroll
            for (int k = 0; k < KW; k++) {
                float wk = wp[k];
                #pragma unroll
                for (int t = 0; t < L2; t++)
                    acc[t] = fmaf(hh[3 * t + k], wk, acc[t]);
            }
        }
        #pragma unroll
        for (int t = 0; t < L2; t++) {
            sY[o * L2 + t] = acc[t];
            bnS += acc[t];
            bnQ = fmaf(acc[t], acc[t], bnQ);
        }
        __syncwarp();
        float* gy2 = g_y2 + (size_t)b * Y2N;
        for (int i = lane; i < Y2N; i += 32) gy2[i] = sY[i];
        __syncwarp();
    }
    atomicAdd(&g_stats[32 + o], bnS);
    atomicAdd(&g_stats[64 + o], bnQ);
}

// ---------------- K3: BN2+tanh, heads, reparam, decoder, output -------------
#define K3_WPB 8
__global__ void __launch_bounds__(K3_WPB * 32) k3_kernel(
    const float* __restrict__ eps,
    const float* __restrict__ mu_w, const float* __restrict__ mu_b,
    const float* __restrict__ lv_w, const float* __restrict__ lv_b,
    const float* __restrict__ de_w1, const float* __restrict__ de_b1,
    const float* __restrict__ de_w2, const float* __restrict__ de_b2,
    const float* __restrict__ bn2_g, const float* __restrict__ bn2_b,
    float* __restrict__ out, int bsz)
{
    __shared__ float s_muw[2 * Y2N], s_lvw[2 * Y2N];
    __shared__ float s_mub[2], s_lvb[2];
    __shared__ float s_dw1[DEH * 2], s_db1[DEH];
    __shared__ float s_dw2[DEOUT * DEH], s_db2[DEOUT];
    __shared__ float s_sc[EN2], s_sh[EN2];
    __shared__ float s_d[K3_WPB][12];

    const int tid = threadIdx.x;
    for (int i = tid; i < 2 * Y2N; i += blockDim.x) { s_muw[i] = mu_w[i]; s_lvw[i] = lv_w[i]; }
    if (tid < 2) { s_mub[tid] = mu_b[tid]; s_lvb[tid] = lv_b[tid]; }
    for (int i = tid; i < DEH * 2; i += blockDim.x) s_dw1[i] = de_w1[i];
    if (tid < DEH) s_db1[tid] = de_b1[tid];
    for (int i = tid; i < DEOUT * DEH; i += blockDim.x) s_dw2[i] = de_w2[i];
    if (tid < DEOUT) s_db2[tid] = de_b2[tid];
    if (tid < EN2) {
        float inv = 1.0f / ((float)bsz * (float)L2);
        float m = g_stats[32 + tid] * inv;
        float v = g_stats[64 + tid] * inv - m * m;
        float r = rsqrtf(v + 1e-5f);
        float sc = bn2_g[tid] * r;
        s_sc[tid] = sc;
        s_sh[tid] = bn2_b[tid] - m * sc;
    }
    __syncthreads();

    const int lane = tid & 31;
    const int w    = tid >> 5;
    const int wpb  = blockDim.x >> 5;
    const int gw   = blockIdx.x * wpb + w;
    const int nw   = gridDim.x * wpb;

    float* outO = out;
    float* outM = out + (size_t)bsz * DEOUT;
    float* outV = out + (size_t)bsz * (DEOUT + 2);

    for (int b = gw; b < bsz; b += nw) {
        const float* gy = g_y2 + (size_t)b * Y2N;
        float pm0 = 0.f, pm1 = 0.f, pl0 = 0.f, pl1 = 0.f;
        #pragma unroll
        for (int j = 0; j < 5; j++) {
            int i = lane + 32 * j;
            int c = i / L2;
            float v = tanhf(fmaf(gy[i], s_sc[c], s_sh[c]));
            pm0 = fmaf(v, s_muw[i], pm0);
            pm1 = fmaf(v, s_muw[Y2N + i], pm1);
            pl0 = fmaf(v, s_lvw[i], pl0);
            pl1 = fmaf(v, s_lvw[Y2N + i], pl1);
        }
        #pragma unroll
        for (int off = 16; off > 0; off >>= 1) {
            pm0 += __shfl_xor_sync(0xffffffffu, pm0, off);
            pm1 += __shfl_xor_sync(0xffffffffu, pm1, off);
            pl0 += __shfl_xor_sync(0xffffffffu, pl0, off);
            pl1 += __shfl_xor_sync(0xffffffffu, pl1, off);
        }
        float mu0 = pm0 + s_mub[0], mu1 = pm1 + s_mub[1];
        float lv0 = pl0 + s_lvb[0], lv1 = pl1 + s_lvb[1];
        float e0 = eps[(size_t)b * 2], e1 = eps[(size_t)b * 2 + 1];
        float z0 = fmaf(e0, expf(0.5f * lv0), mu0);
        float z1 = fmaf(e1, expf(0.5f * lv1), mu1);

        if (lane < DEH)
            s_d[w][lane] = tanhf(fmaf(z0, s_dw1[lane * 2],
                                 fmaf(z1, s_dw1[lane * 2 + 1], s_db1[lane])));
        __syncwarp();
        float dreg[DEH];
        #pragma unroll
        for (int j = 0; j < DEH; j++) dreg[j] = s_d[w][j];

        float* oo = outO + (size_t)b * DEOUT;
        for (int k = lane; k < DEOUT; k += 32) {
            float a = s_db2[k];
            #pragma unroll
            for (int j = 0; j < DEH; j++)
                a = fmaf(dreg[j], s_dw2[k * DEH + j], a);
            oo[k] = tanhf(a);
        }
        if (lane == 0) {
            outM[(size_t)b * 2]     = mu0;
            outM[(size_t)b * 2 + 1] = mu1;
            outV[(size_t)b * 2]     = lv0;
            outV[(size_t)b * 2 + 1] = lv1;
        }
        __syncwarp();
    }
}

extern "C" void kernel_launch(void* const* d_in, const int* in_sizes, int n_in,
                              void* d_out, int out_size)
{
    const float* raw    = (const float*)d_in[0];
    const float* eegf   = (const float*)d_in[1];
    const float* eps    = (const float*)d_in[2];
    const float* fg_w1  = (const float*)d_in[3];
    const float* fg_b1  = (const float*)d_in[4];
    const float* fg_w2  = (const float*)d_in[5];
    const float* fg_b2  = (const float*)d_in[6];
    const float* enc_w1 = (const float*)d_in[7];
    const float* enc_b1 = (const float*)d_in[8];
    const float* bn1_g  = (const float*)d_in[9];
    const float* bn1_b  = (const float*)d_in[10];
    const float* enc_w2 = (const float*)d_in[11];
    const float* enc_b2 = (const float*)d_in[12];
    const float* bn2_g  = (const float*)d_in[13];
    const float* bn2_b  = (const float*)d_in[14];
    const float* mu_w   = (const float*)d_in[15];
    const float* mu_b   = (const float*)d_in[16];
    const float* lv_w   = (const float*)d_in[17];
    const float* lv_b   = (const float*)d_in[18];
    const float* de_w1  = (const float*)d_in[19];
    const float* de_b1  = (const float*)d_in[20];
    const float* de_w2  = (const float*)d_in[21];
    const float* de_b2  = (const float*)d_in[22];

    int bsz = in_sizes[0] / (CH * LRAW);

    zero_stats_kernel<<<1, 128>>>();

    size_t smem1 = (size_t)K1_SMEMF * sizeof(float);
    cudaFuncSetAttribute((const void*)k1_kernel,
                         cudaFuncAttributeMaxDynamicSharedMemorySize, (int)smem1);
    k1_kernel<<<296, K1_WPB * 32, smem1>>>(raw, eegf, fg_w1, fg_b1, fg_w2, fg_b2,
                                           enc_w1, enc_b1, bsz);
    k2_kernel<<<592, K2_WPB * 32>>>(enc_w2, enc_b2, bn1_g, bn1_b, bsz);
    k3_kernel<<<592, K3_WPB * 32>>>(eps, mu_w, mu_b, lv_w, lv_b,
                                    de_w1, de_b1, de_w2, de_b2,
                                    bn2_g, bn2_b, (float*)d_out, bsz);
}

// round 2
// speedup vs baseline: 1.2559x; 1.2559x over previous
#include <cuda_runtime.h>
#include <math.h>

#define BMAX 65536
#define CH 12
#define LRAW 63
#define FLEN 7
#define VLEN 57
#define FIN 168
#define FGH 35
#define EN1 16
#define EN2 32
#define KW 6
#define L1 18
#define L2 5
#define Y1N (EN1 * L1)   // 288
#define Y2N (EN2 * L2)   // 160
#define DEH 10
#define DEOUT 50

// global scratch (allocation-free: __device__ globals)
__device__ float g_y1[(size_t)BMAX * Y1N];   // conv1 pre-activation
__device__ float g_y2[(size_t)BMAX * Y2N];   // conv2 pre-activation
__device__ float g_stats[96];                // [0:16) sum1 [16:32) sq1 [32:64) sum2 [64:96) sq2

__global__ void zero_stats_kernel() {
    if (threadIdx.x < 96) g_stats[threadIdx.x] = 0.0f;
}

// ---------------- packed fp32x2 helpers (sm_103a FFMA2 path) ----------------
__device__ __forceinline__ float2 f2fma(float2 a, float2 b, float2 c) {
    unsigned long long ua = reinterpret_cast<unsigned long long&>(a);
    unsigned long long ub = reinterpret_cast<unsigned long long&>(b);
    unsigned long long uc = reinterpret_cast<unsigned long long&>(c);
    unsigned long long ud;
    asm("fma.rn.f32x2 %0, %1, %2, %3;" : "=l"(ud) : "l"(ua), "l"(ub), "l"(uc));
    return reinterpret_cast<float2&>(ud);
}
__device__ __forceinline__ float2 f2mul(float2 a, float2 b) {
    unsigned long long ua = reinterpret_cast<unsigned long long&>(a);
    unsigned long long ub = reinterpret_cast<unsigned long long&>(b);
    unsigned long long ud;
    asm("mul.rn.f32x2 %0, %1, %2;" : "=l"(ud) : "l"(ua), "l"(ub));
    return reinterpret_cast<float2&>(ud);
}
__device__ __forceinline__ float2 f2add(float2 a, float2 b) {
    unsigned long long ua = reinterpret_cast<unsigned long long&>(a);
    unsigned long long ub = reinterpret_cast<unsigned long long&>(b);
    unsigned long long ud;
    asm("add.rn.f32x2 %0, %1, %2;" : "=l"(ud) : "l"(ua), "l"(ub));
    return reinterpret_cast<float2&>(ud);
}
__device__ __forceinline__ float2 fdup(float x) { return make_float2(x, x); }

// fast accurate tanh: (e^{2x}-1)/(e^{2x}+1), rel err ~1e-6, abs err ~1e-7 near 0
__device__ __forceinline__ float ftanh(float x) {
    float xc = fminf(fmaxf(x, -9.0f), 9.0f);
    float t  = __expf(xc + xc);
    return __fdividef(t - 1.0f, t + 1.0f);
}
__device__ __forceinline__ float2 ftanh2(float2 v) {
    return make_float2(ftanh(v.x), ftanh(v.y));
}

// ---------------- K1: filter-gen + adaptive filter + conv1 + BN1 partials ----
// Each warp processes a SAMPLE PAIR (2p, 2p+1) packed into float2.
// Block-shared (floats):
//   [0,5880)     fg_w1 transposed [168][35]
//   [5880,5916)  fg_b1
//   [5916,6164)  fg_w2
//   [6164,6172)  fg_b2
//   [6172,7340)  enc_w1 padded rows [16][73]
//   [7340,7356)  enc_b1
// Per-warp region (2976 floats):
//   regionA [0,1516):    sRawP f2[756]  (aliases sXP f2[168] and sY1P f2[288])
//   regionB [1516,2888): sEegP f2[684]  (also fgen pass2 scratch)
//   regionC [2888,2976): sH1P f2[36] | sFiltP f2[8]
#define K1_WARPS 6
#define K1_SH_BASE 7356
#define K1_WREG 2976
#define K1_SMEMF (K1_SH_BASE + K1_WARPS * K1_WREG)

__global__ void __launch_bounds__(K1_WARPS * 32) k1_kernel(
    const float* __restrict__ raw, const float* __restrict__ eegf,
    const float* __restrict__ fg_w1, const float* __restrict__ fg_b1,
    const float* __restrict__ fg_w2, const float* __restrict__ fg_b2,
    const float* __restrict__ enc_w1, const float* __restrict__ enc_b1,
    int bsz)
{
    extern __shared__ float sm[];
    float* s_w1T = sm;            // [i*35 + j]
    float* s_b1  = sm + 5880;
    float* s_w2  = sm + 5916;     // [k*35 + i]
    float* s_b2  = sm + 6164;
    float* s_cw  = sm + 6172;     // [o*73 + c*6 + k]
    float* s_cb  = sm + 7340;

    const int tid = threadIdx.x;
    for (int idx = tid; idx < FGH * FIN; idx += blockDim.x) {
        int j = idx / FIN, i = idx - j * FIN;
        s_w1T[i * FGH + j] = fg_w1[idx];
    }
    if (tid < FGH)  s_b1[tid] = fg_b1[tid];
    for (int idx = tid; idx < FLEN * FGH; idx += blockDim.x) s_w2[idx] = fg_w2[idx];
    if (tid < FLEN) s_b2[tid] = fg_b2[tid];
    for (int idx = tid; idx < EN1 * CH * KW; idx += blockDim.x) {
        int o = idx / (CH * KW), r = idx - o * (CH * KW);
        s_cw[o * 73 + r] = enc_w1[idx];
    }
    if (tid < EN1) s_cb[tid] = enc_b1[tid];
    __syncthreads();

    const int lane = tid & 31;
    const int wpb  = blockDim.x >> 5;
    const int gw   = blockIdx.x * wpb + (tid >> 5);
    const int nw   = gridDim.x * wpb;

    float* wbase   = sm + K1_SH_BASE + (tid >> 5) * K1_WREG;
    float2* sRawP  = (float2*)wbase;
    float2* sXP    = (float2*)wbase;                // alias (fgen phase only)
    float2* sY1P   = (float2*)wbase;                // alias (conv1 output phase)
    float2* sEegP  = (float2*)(wbase + 1516);
    float2* sH1P   = (float2*)(wbase + 2888);
    float2* sFiltP = (float2*)(wbase + 2960);

    float2 bnS = make_float2(0.f, 0.f), bnQ = make_float2(0.f, 0.f);
    const int o  = lane >> 1;          // conv1 out channel (0..15)
    const int tb = (lane & 1) * 9;     // conv1 t base (0 or 9)
    const int npairs = bsz >> 1;

    for (int p = gw; p < npairs; p += nw) {
        const int b0 = 2 * p;

        // ---- load eegf pair ----
        const float* ef = eegf + (size_t)b0 * FIN;
        for (int i = lane; i < FIN; i += 32)
            sXP[i] = make_float2(ef[i], ef[i + FIN]);
        __syncwarp();

        // ---- fgen layer1, pass1: j = lane (0..31), 2 accumulators ----
        float2 aa = fdup(s_b1[lane]);
        float2 ab = make_float2(0.f, 0.f);
        #pragma unroll 4
        for (int i = 0; i < FIN; i += 2) {
            aa = f2fma(sXP[i],     fdup(s_w1T[i * FGH + lane]),       aa);
            ab = f2fma(sXP[i + 1], fdup(s_w1T[(i + 1) * FGH + lane]), ab);
        }
        // pass2 partials for j = 32..34 (lanes 0..29, 10-way split per j)
        float2 p2 = make_float2(0.f, 0.f);
        if (lane < 30) {
            int j = 32 + lane / 10;
            for (int i = lane % 10; i < FIN; i += 10)
                p2 = f2fma(sXP[i], fdup(s_w1T[i * FGH + j]), p2);
            sEegP[lane] = p2;   // scratch (eeg not written yet)
        }
        sH1P[lane] = ftanh2(f2add(aa, ab));
        __syncwarp();
        if (lane < 3) {
            float2 a = fdup(s_b1[32 + lane]);
            #pragma unroll
            for (int s = 0; s < 10; s++) a = f2add(a, sEegP[lane * 10 + s]);
            sH1P[32 + lane] = ftanh2(a);
        }
        __syncwarp();

        // ---- fgen layer2: k = lane (<7) ----
        if (lane < FLEN) {
            float2 a = fdup(s_b2[lane]);
            #pragma unroll
            for (int i = 0; i < FGH; i++)
                a = f2fma(sH1P[i], fdup(s_w2[lane * FGH + i]), a);
            sFiltP[lane] = ftanh2(a);
        }
        __syncwarp();
        const float2 f0 = sFiltP[0], f1 = sFiltP[1], f2v = sFiltP[2],
                     f3 = sFiltP[3], f4 = sFiltP[4], f5 = sFiltP[5], f6 = sFiltP[6];

        // ---- load raw pair (overwrites sXP region; fgen done) ----
        const float* rp = raw + (size_t)b0 * (CH * LRAW);
        for (int i = lane; i < CH * LRAW; i += 32)
            sRawP[i] = make_float2(rp[i], rp[i + CH * LRAW]);
        __syncwarp();

        // ---- adaptive 7-tap valid correlation (packed) ----
        for (int idx = lane; idx < CH * VLEN; idx += 32) {
            unsigned c = (unsigned)idx / (unsigned)VLEN;
            unsigned t = (unsigned)idx - c * VLEN;
            const float2* r = sRawP + c * LRAW + t;
            float2 a = f2mul(r[0], f0);
            a = f2fma(r[1], f1, a);  a = f2fma(r[2], f2v, a);
            a = f2fma(r[3], f3, a);  a = f2fma(r[4], f4, a);
            a = f2fma(r[5], f5, a);  a = f2fma(r[6], f6, a);
            sEegP[idx] = a;
        }
        __syncwarp();

        // ---- conv1 (packed): lane = (o, tb), 9 t-positions each ----
        float2 accc[9];
        {
            float2 cb2 = fdup(s_cb[o]);
            #pragma unroll
            for (int i = 0; i < 9; i++) accc[i] = cb2;
        }
        #pragma unroll
        for (int c = 0; c < CH; c++) {
            const float* w = s_cw + o * 73 + c * KW;
            const float2 W0 = fdup(w[0]), W1 = fdup(w[1]), W2 = fdup(w[2]),
                         W3 = fdup(w[3]), W4 = fdup(w[4]), W5 = fdup(w[5]);
            const float2* e = sEegP + c * VLEN + 3 * tb;
            float2 e0 = e[0], e1 = e[1], e2 = e[2], e3 = e[3], e4 = e[4], e5 = e[5];
            #pragma unroll
            for (int i = 0; i < 9; i++) {
                float2 a = accc[i];
                a = f2fma(e0, W0, a); a = f2fma(e1, W1, a); a = f2fma(e2, W2, a);
                a = f2fma(e3, W3, a); a = f2fma(e4, W4, a); a = f2fma(e5, W5, a);
                accc[i] = a;
                if (i < 8) {
                    e0 = e3; e1 = e4; e2 = e5;
                    e3 = e[3 * i + 6]; e4 = e[3 * i + 7]; e5 = e[3 * i + 8];
                }
            }
        }
        #pragma unroll
        for (int i = 0; i < 9; i++) sY1P[o * L1 + tb + i] = accc[i];  // raw dead
        __syncwarp();

        // ---- store y1 pair (coalesced) + BN1 partials ----
        float* gA = g_y1 + (size_t)b0 * Y1N;
        for (int i = lane; i < Y1N; i += 32) {
            float2 v = sY1P[i];
            gA[i] = v.x; gA[i + Y1N] = v.y;
        }
        if (lane < EN1) {
            #pragma unroll
            for (int t = 0; t < L1; t++) {
                float2 v = sY1P[lane * L1 + t];
                bnS = f2add(bnS, v);
                bnQ = f2fma(v, v, bnQ);
            }
        }
        __syncwarp();
    }
    if (lane < EN1) {
        atomicAdd(&g_stats[lane],       bnS.x + bnS.y);
        atomicAdd(&g_stats[EN1 + lane], bnQ.x + bnQ.y);
    }
}

// ---------------- K2: BN1+tanh, conv2 (packed pairs), BN2 partials ----------
#define K2_WARPS 8
__global__ void __launch_bounds__(K2_WARPS * 32) k2_kernel(
    const float* __restrict__ enc_w2, const float* __restrict__ enc_b2,
    const float* __restrict__ bn1_g, const float* __restrict__ bn1_b,
    int bsz)
{
    __shared__ float  s_w[EN2 * 97];          // [o*97 + c*6 + k]
    __shared__ float  s_b[EN2];
    __shared__ float2 s_scP[EN1], s_shP[EN1];
    __shared__ float2 s_buf[K2_WARPS][448];   // per warp: sHP f2[288] | sYP f2[160]

    const int tid = threadIdx.x;
    for (int idx = tid; idx < EN2 * EN1 * KW; idx += blockDim.x) {
        int o = idx / (EN1 * KW), r = idx - o * (EN1 * KW);
        s_w[o * 97 + r] = enc_w2[idx];
    }
    if (tid < EN2) s_b[tid] = enc_b2[tid];
    if (tid < EN1) {
        float inv = 1.0f / ((float)bsz * (float)L1);
        float m = g_stats[tid] * inv;
        float v = g_stats[EN1 + tid] * inv - m * m;
        float r = rsqrtf(v + 1e-5f);
        float sc = bn1_g[tid] * r;
        s_scP[tid] = fdup(sc);
        s_shP[tid] = fdup(bn1_b[tid] - m * sc);
    }
    __syncthreads();

    const int lane = tid & 31;
    const int w    = tid >> 5;
    const int wpb  = blockDim.x >> 5;
    const int gw   = blockIdx.x * wpb + w;
    const int nw   = gridDim.x * wpb;
    float2* sHP = s_buf[w];
    float2* sYP = s_buf[w] + Y1N;

    float2 bnS = make_float2(0.f, 0.f), bnQ = make_float2(0.f, 0.f);
    const int o = lane;   // conv2 out channel 0..31
    const int npairs = bsz >> 1;

    for (int p = gw; p < npairs; p += nw) {
        const float* gy = g_y1 + (size_t)(2 * p) * Y1N;
        #pragma unroll 3
        for (int i = lane; i < Y1N; i += 32) {
            unsigned c = (unsigned)i / 18u;
            float2 y = make_float2(gy[i], gy[i + Y1N]);
            sHP[i] = ftanh2(f2fma(y, s_scP[c], s_shP[c]));
        }
        __syncwarp();

        float2 acc[L2];
        {
            float2 b2 = fdup(s_b[o]);
            #pragma unroll
            for (int t = 0; t < L2; t++) acc[t] = b2;
        }
        #pragma unroll
        for (int c = 0; c < EN1; c++) {
            const float* wp = s_w + o * 97 + c * KW;
            float2 W[KW];
            #pragma unroll
            for (int k = 0; k < KW; k++) W[k] = fdup(wp[k]);
            const float2* h = sHP + c * L1;
            float2 hh[L1];
            #pragma unroll
            for (int x = 0; x < L1; x++) hh[x] = h[x];
            #pragma unroll
            for (int k = 0; k < KW; k++) {
                #pragma unroll
                for (int t = 0; t < L2; t++)
                    acc[t] = f2fma(hh[3 * t + k], W[k], acc[t]);
            }
        }
        #pragma unroll
        for (int t = 0; t < L2; t++) {
            sYP[o * L2 + t] = acc[t];
            bnS = f2add(bnS, acc[t]);
            bnQ = f2fma(acc[t], acc[t], bnQ);
        }
        __syncwarp();
        float* g2 = g_y2 + (size_t)(2 * p) * Y2N;
        for (int i = lane; i < Y2N; i += 32) {
            float2 v = sYP[i];
            g2[i] = v.x; g2[i + Y2N] = v.y;
        }
        __syncwarp();
    }
    atomicAdd(&g_stats[32 + o], bnS.x + bnS.y);
    atomicAdd(&g_stats[64 + o], bnQ.x + bnQ.y);
}

// ---------------- K3: BN2+tanh, heads, reparam, decoder, output -------------
#define K3_WPB 8
__global__ void __launch_bounds__(K3_WPB * 32) k3_kernel(
    const float* __restrict__ eps,
    const float* __restrict__ mu_w, const float* __restrict__ mu_b,
    const float* __restrict__ lv_w, const float* __restrict__ lv_b,
    const float* __restrict__ de_w1, const float* __restrict__ de_b1,
    const float* __restrict__ de_w2, const float* __restrict__ de_b2,
    const float* __restrict__ bn2_g, const float* __restrict__ bn2_b,
    float* __restrict__ out, int bsz)
{
    __shared__ float s_muw[2 * Y2N], s_lvw[2 * Y2N];
    __shared__ float s_mub[2], s_lvb[2];
    __shared__ float s_dw1[DEH * 2], s_db1[DEH];
    __shared__ float s_dw2[DEOUT * DEH], s_db2[DEOUT];
    __shared__ float s_sc[EN2], s_sh[EN2];
    __shared__ float s_d[K3_WPB][12];

    const int tid = threadIdx.x;
    for (int i = tid; i < 2 * Y2N; i += blockDim.x) { s_muw[i] = mu_w[i]; s_lvw[i] = lv_w[i]; }
    if (tid < 2) { s_mub[tid] = mu_b[tid]; s_lvb[tid] = lv_b[tid]; }
    for (int i = tid; i < DEH * 2; i += blockDim.x) s_dw1[i] = de_w1[i];
    if (tid < DEH) s_db1[tid] = de_b1[tid];
    for (int i = tid; i < DEOUT * DEH; i += blockDim.x) s_dw2[i] = de_w2[i];
    if (tid < DEOUT) s_db2[tid] = de_b2[tid];
    if (tid < EN2) {
        float inv = 1.0f / ((float)bsz * (float)L2);
        float m = g_stats[32 + tid] * inv;
        float v = g_stats[64 + tid] * inv - m * m;
        float r = rsqrtf(v + 1e-5f);
        float sc = bn2_g[tid] * r;
        s_sc[tid] = sc;
        s_sh[tid] = bn2_b[tid] - m * sc;
    }
    __syncthreads();

    const int lane = tid & 31;
    const int w    = tid >> 5;
    const int wpb  = blockDim.x >> 5;
    const int gw   = blockIdx.x * wpb + w;
    const int nw   = gridDim.x * wpb;

    float* outO = out;
    float* outM = out + (size_t)bsz * DEOUT;
    float* outV = out + (size_t)bsz * (DEOUT + 2);

    for (int b = gw; b < bsz; b += nw) {
        const float* gy = g_y2 + (size_t)b * Y2N;
        float pm0 = 0.f, pm1 = 0.f, pl0 = 0.f, pl1 = 0.f;
        #pragma unroll
        for (int j = 0; j < 5; j++) {
            int i = lane + 32 * j;
            int c = i / L2;
            float v = ftanh(fmaf(gy[i], s_sc[c], s_sh[c]));
            pm0 = fmaf(v, s_muw[i], pm0);
            pm1 = fmaf(v, s_muw[Y2N + i], pm1);
            pl0 = fmaf(v, s_lvw[i], pl0);
            pl1 = fmaf(v, s_lvw[Y2N + i], pl1);
        }
        #pragma unroll
        for (int off = 16; off > 0; off >>= 1) {
            pm0 += __shfl_xor_sync(0xffffffffu, pm0, off);
            pm1 += __shfl_xor_sync(0xffffffffu, pm1, off);
            pl0 += __shfl_xor_sync(0xffffffffu, pl0, off);
            pl1 += __shfl_xor_sync(0xffffffffu, pl1, off);
        }
        float mu0 = pm0 + s_mub[0], mu1 = pm1 + s_mub[1];
        float lv0 = pl0 + s_lvb[0], lv1 = pl1 + s_lvb[1];
        float e0 = eps[(size_t)b * 2], e1 = eps[(size_t)b * 2 + 1];
        float z0 = fmaf(e0, __expf(0.5f * lv0), mu0);
        float z1 = fmaf(e1, __expf(0.5f * lv1), mu1);

        if (lane < DEH)
            s_d[w][lane] = ftanh(fmaf(z0, s_dw1[lane * 2],
                                 fmaf(z1, s_dw1[lane * 2 + 1], s_db1[lane])));
        __syncwarp();
        float dreg[DEH];
        #pragma unroll
        for (int j = 0; j < DEH; j++) dreg[j] = s_d[w][j];

        float* oo = outO + (size_t)b * DEOUT;
        for (int k = lane; k < DEOUT; k += 32) {
            float a = s_db2[k];
            #pragma unroll
            for (int j = 0; j < DEH; j++)
                a = fmaf(dreg[j], s_dw2[k * DEH + j], a);
            oo[k] = ftanh(a);
        }
        if (lane == 0) {
            outM[(size_t)b * 2]     = mu0;
            outM[(size_t)b * 2 + 1] = mu1;
            outV[(size_t)b * 2]     = lv0;
            outV[(size_t)b * 2 + 1] = lv1;
        }
        __syncwarp();
    }
}

extern "C" void kernel_launch(void* const* d_in, const int* in_sizes, int n_in,
                              void* d_out, int out_size)
{
    const float* raw    = (const float*)d_in[0];
    const float* eegf   = (const float*)d_in[1];
    const float* eps    = (const float*)d_in[2];
    const float* fg_w1  = (const float*)d_in[3];
    const float* fg_b1  = (const float*)d_in[4];
    const float* fg_w2  = (const float*)d_in[5];
    const float* fg_b2  = (const float*)d_in[6];
    const float* enc_w1 = (const float*)d_in[7];
    const float* enc_b1 = (const float*)d_in[8];
    const float* bn1_g  = (const float*)d_in[9];
    const float* bn1_b  = (const float*)d_in[10];
    const float* enc_w2 = (const float*)d_in[11];
    const float* enc_b2 = (const float*)d_in[12];
    const float* bn2_g  = (const float*)d_in[13];
    const float* bn2_b  = (const float*)d_in[14];
    const float* mu_w   = (const float*)d_in[15];
    const float* mu_b   = (const float*)d_in[16];
    const float* lv_w   = (const float*)d_in[17];
    const float* lv_b   = (const float*)d_in[18];
    const float* de_w1  = (const float*)d_in[19];
    const float* de_b1  = (const float*)d_in[20];
    const float* de_w2  = (const float*)d_in[21];
    const float* de_b2  = (const float*)d_in[22];

    int bsz = in_sizes[0] / (CH * LRAW);

    zero_stats_kernel<<<1, 128>>>();

    size_t smem1 = (size_t)K1_SMEMF * sizeof(float);
    cudaFuncSetAttribute((const void*)k1_kernel,
                         cudaFuncAttributeMaxDynamicSharedMemorySize, (int)smem1);
    k1_kernel<<<296, K1_WARPS * 32, smem1>>>(raw, eegf, fg_w1, fg_b1, fg_w2, fg_b2,
                                             enc_w1, enc_b1, bsz);
    k2_kernel<<<296, K2_WARPS * 32>>>(enc_w2, enc_b2, bn1_g, bn1_b, bsz);
    k3_kernel<<<592, K3_WPB * 32>>>(eps, mu_w, mu_b, lv_w, lv_b,
                                    de_w1, de_b1, de_w2, de_b2,
                                    bn2_g, bn2_b, (float*)d_out, bsz);
}

// round 3
// speedup vs baseline: 1.5501x; 1.2342x over previous
#include <cuda_runtime.h>
#include <math.h>

#define BMAX 65536
#define CH 12
#define LRAW 63
#define FLEN 7
#define VLEN 57
#define FIN 168
#define FGH 35
#define EN1 16
#define EN2 32
#define KW 6
#define L1 18
#define L2 5
#define Y1N (EN1 * L1)   // 288
#define Y2N (EN2 * L2)   // 160
#define DEH 10
#define DEOUT 50

// global scratch (allocation-free: __device__ globals)
__device__ float g_filt[(size_t)FLEN * BMAX];   // transposed [k][B]
__device__ float g_y1[(size_t)BMAX * Y1N];      // conv1 pre-activation
__device__ float g_y2[(size_t)BMAX * Y2N];      // conv2 pre-activation
__device__ float g_stats[96];                   // sums/sqsums for BN1/BN2

__global__ void zero_stats_kernel() {
    if (threadIdx.x < 96) g_stats[threadIdx.x] = 0.0f;
}

// ---------------- packed fp32x2 helpers (sm_103a FFMA2 path) ----------------
__device__ __forceinline__ float2 f2fma(float2 a, float2 b, float2 c) {
    unsigned long long ua = reinterpret_cast<unsigned long long&>(a);
    unsigned long long ub = reinterpret_cast<unsigned long long&>(b);
    unsigned long long uc = reinterpret_cast<unsigned long long&>(c);
    unsigned long long ud;
    asm("fma.rn.f32x2 %0, %1, %2, %3;" : "=l"(ud) : "l"(ua), "l"(ub), "l"(uc));
    return reinterpret_cast<float2&>(ud);
}
__device__ __forceinline__ float2 f2mul(float2 a, float2 b) {
    unsigned long long ua = reinterpret_cast<unsigned long long&>(a);
    unsigned long long ub = reinterpret_cast<unsigned long long&>(b);
    unsigned long long ud;
    asm("mul.rn.f32x2 %0, %1, %2;" : "=l"(ud) : "l"(ua), "l"(ub));
    return reinterpret_cast<float2&>(ud);
}
__device__ __forceinline__ float2 f2add(float2 a, float2 b) {
    unsigned long long ua = reinterpret_cast<unsigned long long&>(a);
    unsigned long long ub = reinterpret_cast<unsigned long long&>(b);
    unsigned long long ud;
    asm("add.rn.f32x2 %0, %1, %2;" : "=l"(ud) : "l"(ua), "l"(ub));
    return reinterpret_cast<float2&>(ud);
}
__device__ __forceinline__ float2 fdup(float x) { return make_float2(x, x); }

// fast accurate tanh: (e^{2x}-1)/(e^{2x}+1), rel err ~1e-6
__device__ __forceinline__ float ftanh(float x) {
    float xc = fminf(fmaxf(x, -9.0f), 9.0f);
    float t  = __expf(xc + xc);
    return __fdividef(t - 1.0f, t + 1.0f);
}
__device__ __forceinline__ float2 ftanh2(float2 v) {
    return make_float2(ftanh(v.x), ftanh(v.y));
}

// ================= K1a: filter generator, 4 samples per warp ================
// shared (floats):
//   [0,5880)     fg_w1 transposed [168][35]
//   [5880,5916)  fg_b1
//   [5916,6164)  fg_w2 (padded)
//   [6164,6172)  fg_b2
//   per-warp (944 floats):
//     sXA f2[168] | sXB f2[168] | sH1A f2[36] | sH1B f2[36] | sP2A f2[30] | sP2B f2[30]
#define K1A_WARPS 16
#define K1A_BASE 6172
#define K1A_WREG 944
#define K1A_SMEMF (K1A_BASE + K1A_WARPS * K1A_WREG)

__global__ void __launch_bounds__(K1A_WARPS * 32) k1a_kernel(
    const float* __restrict__ eegf,
    const float* __restrict__ fg_w1, const float* __restrict__ fg_b1,
    const float* __restrict__ fg_w2, const float* __restrict__ fg_b2,
    int bsz)
{
    extern __shared__ float sm[];
    float* s_w1T = sm;
    float* s_b1  = sm + 5880;
    float* s_w2  = sm + 5916;
    float* s_b2  = sm + 6164;

    const int tid = threadIdx.x;
    for (int idx = tid; idx < FGH * FIN; idx += blockDim.x) {
        int j = idx / FIN, i = idx - j * FIN;
        s_w1T[i * FGH + j] = fg_w1[idx];
    }
    if (tid < FGH)  s_b1[tid] = fg_b1[tid];
    for (int idx = tid; idx < FLEN * FGH; idx += blockDim.x) s_w2[idx] = fg_w2[idx];
    if (tid < FLEN) s_b2[tid] = fg_b2[tid];
    __syncthreads();

    const int lane = tid & 31;
    const int wpb  = blockDim.x >> 5;
    const int gw   = blockIdx.x * wpb + (tid >> 5);
    const int nw   = gridDim.x * wpb;

    float* wbase = sm + K1A_BASE + (tid >> 5) * K1A_WREG;
    float2* sXA  = (float2*)wbase;
    float2* sXB  = (float2*)(wbase + 336);
    float2* sH1A = (float2*)(wbase + 672);
    float2* sH1B = (float2*)(wbase + 744);
    float2* sP2A = (float2*)(wbase + 816);
    float2* sP2B = (float2*)(wbase + 876);

    const int npairs = bsz >> 1;
    const int nquads = (npairs + 1) >> 1;

    for (int q = gw; q < nquads; q += nw) {
        const int pA = 2 * q;
        const int pB = (2 * q + 1 < npairs) ? 2 * q + 1 : 2 * q;
        const int bA = 2 * pA, bB = 2 * pB;

        const float* efA0 = eegf + (size_t)bA * FIN;
        const float* efA1 = efA0 + FIN;
        const float* efB0 = eegf + (size_t)bB * FIN;
        const float* efB1 = efB0 + FIN;
        for (int i = lane; i < FIN; i += 32) {
            sXA[i] = make_float2(efA0[i], efA1[i]);
            sXB[i] = make_float2(efB0[i], efB1[i]);
        }
        __syncwarp();

        // fgen layer1 pass1: j = lane
        float2 aA = fdup(s_b1[lane]);
        float2 aB = aA;
        #pragma unroll 4
        for (int i = 0; i < FIN; i++) {
            float2 wv = fdup(s_w1T[i * FGH + lane]);
            aA = f2fma(sXA[i], wv, aA);
            aB = f2fma(sXB[i], wv, aB);
        }
        // pass2 partials (j = 32..34, 10-way split)
        if (lane < 30) {
            int j = 32 + lane / 10;
            float2 pA2 = make_float2(0.f, 0.f), pB2 = make_float2(0.f, 0.f);
            for (int i = lane % 10; i < FIN; i += 10) {
                float2 wv = fdup(s_w1T[i * FGH + j]);
                pA2 = f2fma(sXA[i], wv, pA2);
                pB2 = f2fma(sXB[i], wv, pB2);
            }
            sP2A[lane] = pA2; sP2B[lane] = pB2;
        }
        sH1A[lane] = ftanh2(aA);
        sH1B[lane] = ftanh2(aB);
        __syncwarp();
        if (lane < 3) {
            float2 tA = fdup(s_b1[32 + lane]);
            float2 tB = tA;
            #pragma unroll
            for (int s = 0; s < 10; s++) {
                tA = f2add(tA, sP2A[lane * 10 + s]);
                tB = f2add(tB, sP2B[lane * 10 + s]);
            }
            sH1A[32 + lane] = ftanh2(tA);
            sH1B[32 + lane] = ftanh2(tB);
        }
        __syncwarp();

        // fgen layer2: k = lane (<7), write transposed filt
        if (lane < FLEN) {
            float2 cA = fdup(s_b2[lane]);
            float2 cB = cA;
            #pragma unroll
            for (int i = 0; i < FGH; i++) {
                float2 wv = fdup(s_w2[lane * FGH + i]);
                cA = f2fma(sH1A[i], wv, cA);
                cB = f2fma(sH1B[i], wv, cB);
            }
            float* gf = g_filt + (size_t)lane * bsz;
            *(float2*)(gf + bA) = ftanh2(cA);
            *(float2*)(gf + bB) = ftanh2(cB);
        }
        __syncwarp();
    }
}

// ============ K1b: adaptive 7-tap filter + conv1 + BN1 partials =============
// shared (floats):
//   [0,1168)   enc_w1 padded rows [16][73]
//   [1168,1184) enc_b1 ; pad to 1192
//   per-warp (2888 floats): sRawP f2[756] (alias sY1P f2[288]) | sEegP f2[684]+pad
#define K1B_WARPS 8
#define K1B_BASE 1192
#define K1B_WREG 2888
#define K1B_SMEMF (K1B_BASE + K1B_WARPS * K1B_WREG)

__global__ void __launch_bounds__(K1B_WARPS * 32) k1b_kernel(
    const float* __restrict__ raw,
    const float* __restrict__ enc_w1, const float* __restrict__ enc_b1,
    int bsz)
{
    extern __shared__ float sm[];
    float* s_cw = sm;             // [o*73 + c*6 + k]
    float* s_cb = sm + 1168;

    const int tid = threadIdx.x;
    for (int idx = tid; idx < EN1 * CH * KW; idx += blockDim.x) {
        int o = idx / (CH * KW), r = idx - o * (CH * KW);
        s_cw[o * 73 + r] = enc_w1[idx];
    }
    if (tid < EN1) s_cb[tid] = enc_b1[tid];
    __syncthreads();

    const int lane = tid & 31;
    const int wpb  = blockDim.x >> 5;
    const int gw   = blockIdx.x * wpb + (tid >> 5);
    const int nw   = gridDim.x * wpb;

    float* wbase  = sm + K1B_BASE + (tid >> 5) * K1B_WREG;
    float2* sRawP = (float2*)wbase;
    float2* sY1P  = (float2*)wbase;          // alias: raw dead by conv1 output
    float2* sEegP = (float2*)(wbase + 1512);

    float2 bnS = make_float2(0.f, 0.f), bnQ = make_float2(0.f, 0.f);
    const int o  = lane >> 1;
    const int tb = (lane & 1) * 9;
    const int npairs = bsz >> 1;

    for (int p = gw; p < npairs; p += nw) {
        const int b0 = 2 * p;

        // filt taps (broadcast loads from transposed layout)
        const float* gf = g_filt;
        const float2 f0 = *(const float2*)(gf + 0 * (size_t)bsz + b0);
        const float2 f1 = *(const float2*)(gf + 1 * (size_t)bsz + b0);
        const float2 f2v= *(const float2*)(gf + 2 * (size_t)bsz + b0);
        const float2 f3 = *(const float2*)(gf + 3 * (size_t)bsz + b0);
        const float2 f4 = *(const float2*)(gf + 4 * (size_t)bsz + b0);
        const float2 f5 = *(const float2*)(gf + 5 * (size_t)bsz + b0);
        const float2 f6 = *(const float2*)(gf + 6 * (size_t)bsz + b0);

        // load raw pair
        const float* rp = raw + (size_t)b0 * (CH * LRAW);
        for (int i = lane; i < CH * LRAW; i += 32)
            sRawP[i] = make_float2(rp[i], rp[i + CH * LRAW]);
        __syncwarp();

        // adaptive 7-tap valid correlation (packed)
        for (int idx = lane; idx < CH * VLEN; idx += 32) {
            unsigned c = (unsigned)idx / (unsigned)VLEN;
            unsigned t = (unsigned)idx - c * VLEN;
            const float2* r = sRawP + c * LRAW + t;
            float2 a = f2mul(r[0], f0);
            a = f2fma(r[1], f1, a);  a = f2fma(r[2], f2v, a);
            a = f2fma(r[3], f3, a);  a = f2fma(r[4], f4, a);
            a = f2fma(r[5], f5, a);  a = f2fma(r[6], f6, a);
            sEegP[idx] = a;
        }
        __syncwarp();

        // conv1 (packed): lane = (o, tb), 9 t-positions
        float2 accc[9];
        {
            float2 cb2 = fdup(s_cb[o]);
            #pragma unroll
            for (int i = 0; i < 9; i++) accc[i] = cb2;
        }
        #pragma unroll
        for (int c = 0; c < CH; c++) {
            const float* w = s_cw + o * 73 + c * KW;
            const float2 W0 = fdup(w[0]), W1 = fdup(w[1]), W2 = fdup(w[2]),
                         W3 = fdup(w[3]), W4 = fdup(w[4]), W5 = fdup(w[5]);
            const float2* e = sEegP + c * VLEN + 3 * tb;
            float2 e0 = e[0], e1 = e[1], e2 = e[2], e3 = e[3], e4 = e[4], e5 = e[5];
            #pragma unroll
            for (int i = 0; i < 9; i++) {
                float2 a = accc[i];
                a = f2fma(e0, W0, a); a = f2fma(e1, W1, a); a = f2fma(e2, W2, a);
                a = f2fma(e3, W3, a); a = f2fma(e4, W4, a); a = f2fma(e5, W5, a);
                accc[i] = a;
                if (i < 8) {
                    e0 = e3; e1 = e4; e2 = e5;
                    e3 = e[3 * i + 6]; e4 = e[3 * i + 7]; e5 = e[3 * i + 8];
                }
            }
        }
        #pragma unroll
        for (int i = 0; i < 9; i++) sY1P[o * L1 + tb + i] = accc[i];
        __syncwarp();

        float* gA = g_y1 + (size_t)b0 * Y1N;
        for (int i = lane; i < Y1N; i += 32) {
            float2 v = sY1P[i];
            gA[i] = v.x; gA[i + Y1N] = v.y;
        }
        if (lane < EN1) {
            #pragma unroll
            for (int t = 0; t < L1; t++) {
                float2 v = sY1P[lane * L1 + t];
                bnS = f2add(bnS, v);
                bnQ = f2fma(v, v, bnQ);
            }
        }
        __syncwarp();
    }
    if (lane < EN1) {
        atomicAdd(&g_stats[lane],       bnS.x + bnS.y);
        atomicAdd(&g_stats[EN1 + lane], bnQ.x + bnQ.y);
    }
}

// ---------------- K2: BN1+tanh, conv2 (packed pairs), BN2 partials ----------
#define K2_WARPS 8
__global__ void __launch_bounds__(K2_WARPS * 32) k2_kernel(
    const float* __restrict__ enc_w2, const float* __restrict__ enc_b2,
    const float* __restrict__ bn1_g, const float* __restrict__ bn1_b,
    int bsz)
{
    __shared__ float  s_w[EN2 * 97];
    __shared__ float  s_b[EN2];
    __shared__ float2 s_scP[EN1], s_shP[EN1];
    __shared__ __align__(16) float2 s_buf[K2_WARPS][448];  // sHP f2[288] | sYP f2[160]

    const int tid = threadIdx.x;
    for (int idx = tid; idx < EN2 * EN1 * KW; idx += blockDim.x) {
        int o = idx / (EN1 * KW), r = idx - o * (EN1 * KW);
        s_w[o * 97 + r] = enc_w2[idx];
    }
    if (tid < EN2) s_b[tid] = enc_b2[tid];
    if (tid < EN1) {
        float inv = 1.0f / ((float)bsz * (float)L1);
        float m = g_stats[tid] * inv;
        float v = g_stats[EN1 + tid] * inv - m * m;
        float r = rsqrtf(v + 1e-5f);
        float sc = bn1_g[tid] * r;
        s_scP[tid] = fdup(sc);
        s_shP[tid] = fdup(bn1_b[tid] - m * sc);
    }
    __syncthreads();

    const int lane = tid & 31;
    const int w    = tid >> 5;
    const int wpb  = blockDim.x >> 5;
    const int gw   = blockIdx.x * wpb + w;
    const int nw   = gridDim.x * wpb;
    float2* sHP = s_buf[w];
    float2* sYP = s_buf[w] + Y1N;

    float2 bnS = make_float2(0.f, 0.f), bnQ = make_float2(0.f, 0.f);
    const int o = lane;
    const int npairs = bsz >> 1;

    for (int p = gw; p < npairs; p += nw) {
        const float* gy = g_y1 + (size_t)(2 * p) * Y1N;
        #pragma unroll 3
        for (int i = lane; i < Y1N; i += 32) {
            unsigned c = (unsigned)i / 18u;
            float2 y = make_float2(gy[i], gy[i + Y1N]);
            sHP[i] = ftanh2(f2fma(y, s_scP[c], s_shP[c]));
        }
        __syncwarp();

        float2 acc[L2];
        {
            float2 b2 = fdup(s_b[o]);
            #pragma unroll
            for (int t = 0; t < L2; t++) acc[t] = b2;
        }
        #pragma unroll
        for (int c = 0; c < EN1; c++) {
            const float* wp = s_w + o * 97 + c * KW;
            float2 W[KW];
            #pragma unroll
            for (int k = 0; k < KW; k++) W[k] = fdup(wp[k]);
            // vectorized row fetch: 9 x LDS.128
            const float4* h4 = reinterpret_cast<const float4*>(sHP + c * L1);
            float2 hh[L1];
            #pragma unroll
            for (int x = 0; x < 9; x++) {
                float4 q = h4[x];
                hh[2 * x]     = make_float2(q.x, q.y);
                hh[2 * x + 1] = make_float2(q.z, q.w);
            }
            #pragma unroll
            for (int k = 0; k < KW; k++) {
                #pragma unroll
                for (int t = 0; t < L2; t++)
                    acc[t] = f2fma(hh[3 * t + k], W[k], acc[t]);
            }
        }
        #pragma unroll
        for (int t = 0; t < L2; t++) {
            sYP[o * L2 + t] = acc[t];
            bnS = f2add(bnS, acc[t]);
            bnQ = f2fma(acc[t], acc[t], bnQ);
        }
        __syncwarp();
        float* g2 = g_y2 + (size_t)(2 * p) * Y2N;
        for (int i = lane; i < Y2N; i += 32) {
            float2 v = sYP[i];
            g2[i] = v.x; g2[i + Y2N] = v.y;
        }
        __syncwarp();
    }
    atomicAdd(&g_stats[32 + o], bnS.x + bnS.y);
    atomicAdd(&g_stats[64 + o], bnQ.x + bnQ.y);
}

// ---------------- K3: BN2+tanh, heads, reparam, decoder, output -------------
#define K3_WPB 8
__global__ void __launch_bounds__(K3_WPB * 32) k3_kernel(
    const float* __restrict__ eps,
    const float* __restrict__ mu_w, const float* __restrict__ mu_b,
    const float* __restrict__ lv_w, const float* __restrict__ lv_b,
    const float* __restrict__ de_w1, const float* __restrict__ de_b1,
    const float* __restrict__ de_w2, const float* __restrict__ de_b2,
    const float* __restrict__ bn2_g, const float* __restrict__ bn2_b,
    float* __restrict__ out, int bsz)
{
    __shared__ float s_muw[2 * Y2N], s_lvw[2 * Y2N];
    __shared__ float s_mub[2], s_lvb[2];
    __shared__ float s_dw1[DEH * 2], s_db1[DEH];
    __shared__ float s_dw2[DEOUT * DEH], s_db2[DEOUT];
    __shared__ float s_sc[EN2], s_sh[EN2];
    __shared__ float s_d[K3_WPB][12];

    const int tid = threadIdx.x;
    for (int i = tid; i < 2 * Y2N; i += blockDim.x) { s_muw[i] = mu_w[i]; s_lvw[i] = lv_w[i]; }
    if (tid < 2) { s_mub[tid] = mu_b[tid]; s_lvb[tid] = lv_b[tid]; }
    for (int i = tid; i < DEH * 2; i += blockDim.x) s_dw1[i] = de_w1[i];
    if (tid < DEH) s_db1[tid] = de_b1[tid];
    for (int i = tid; i < DEOUT * DEH; i += blockDim.x) s_dw2[i] = de_w2[i];
    if (tid < DEOUT) s_db2[tid] = de_b2[tid];
    if (tid < EN2) {
        float inv = 1.0f / ((float)bsz * (float)L2);
        float m = g_stats[32 + tid] * inv;
        float v = g_stats[64 + tid] * inv - m * m;
        float r = rsqrtf(v + 1e-5f);
        float sc = bn2_g[tid] * r;
        s_sc[tid] = sc;
        s_sh[tid] = bn2_b[tid] - m * sc;
    }
    __syncthreads();

    const int lane = tid & 31;
    const int w    = tid >> 5;
    const int wpb  = blockDim.x >> 5;
    const int gw   = blockIdx.x * wpb + w;
    const int nw   = gridDim.x * wpb;

    float* outO = out;
    float* outM = out + (size_t)bsz * DEOUT;
    float* outV = out + (size_t)bsz * (DEOUT + 2);

    for (int b = gw; b < bsz; b += nw) {
        const float* gy = g_y2 + (size_t)b * Y2N;
        float pm0 = 0.f, pm1 = 0.f, pl0 = 0.f, pl1 = 0.f;
        #pragma unroll
        for (int j = 0; j < 5; j++) {
            int i = lane + 32 * j;
            int c = i / L2;
            float v = ftanh(fmaf(gy[i], s_sc[c], s_sh[c]));
            pm0 = fmaf(v, s_muw[i], pm0);
            pm1 = fmaf(v, s_muw[Y2N + i], pm1);
            pl0 = fmaf(v, s_lvw[i], pl0);
            pl1 = fmaf(v, s_lvw[Y2N + i], pl1);
        }
        #pragma unroll
        for (int off = 16; off > 0; off >>= 1) {
            pm0 += __shfl_xor_sync(0xffffffffu, pm0, off);
            pm1 += __shfl_xor_sync(0xffffffffu, pm1, off);
            pl0 += __shfl_xor_sync(0xffffffffu, pl0, off);
            pl1 += __shfl_xor_sync(0xffffffffu, pl1, off);
        }
        float mu0 = pm0 + s_mub[0], mu1 = pm1 + s_mub[1];
        float lv0 = pl0 + s_lvb[0], lv1 = pl1 + s_lvb[1];
        float e0 = eps[(size_t)b * 2], e1 = eps[(size_t)b * 2 + 1];
        float z0 = fmaf(e0, __expf(0.5f * lv0), mu0);
        float z1 = fmaf(e1, __expf(0.5f * lv1), mu1);

        if (lane < DEH)
            s_d[w][lane] = ftanh(fmaf(z0, s_dw1[lane * 2],
                                 fmaf(z1, s_dw1[lane * 2 + 1], s_db1[lane])));
        __syncwarp();
        float dreg[DEH];
        #pragma unroll
        for (int j = 0; j < DEH; j++) dreg[j] = s_d[w][j];

        float* oo = outO + (size_t)b * DEOUT;
        for (int k = lane; k < DEOUT; k += 32) {
            float a = s_db2[k];
            #pragma unroll
            for (int j = 0; j < DEH; j++)
                a = fmaf(dreg[j], s_dw2[k * DEH + j], a);
            oo[k] = ftanh(a);
        }
        if (lane == 0) {
            outM[(size_t)b * 2]     = mu0;
            outM[(size_t)b * 2 + 1] = mu1;
            outV[(size_t)b * 2]     = lv0;
            outV[(size_t)b * 2 + 1] = lv1;
        }
        __syncwarp();
    }
}

extern "C" void kernel_launch(void* const* d_in, const int* in_sizes, int n_in,
                              void* d_out, int out_size)
{
    const float* raw    = (const float*)d_in[0];
    const float* eegf   = (const float*)d_in[1];
    const float* eps    = (const float*)d_in[2];
    const float* fg_w1  = (const float*)d_in[3];
    const float* fg_b1  = (const float*)d_in[4];
    const float* fg_w2  = (const float*)d_in[5];
    const float* fg_b2  = (const float*)d_in[6];
    const float* enc_w1 = (const float*)d_in[7];
    const float* enc_b1 = (const float*)d_in[8];
    const float* bn1_g  = (const float*)d_in[9];
    const float* bn1_b  = (const float*)d_in[10];
    const float* enc_w2 = (const float*)d_in[11];
    const float* enc_b2 = (const float*)d_in[12];
    const float* bn2_g  = (const float*)d_in[13];
    const float* bn2_b  = (const float*)d_in[14];
    const float* mu_w   = (const float*)d_in[15];
    const float* mu_b   = (const float*)d_in[16];
    const float* lv_w   = (const float*)d_in[17];
    const float* lv_b   = (const float*)d_in[18];
    const float* de_w1  = (const float*)d_in[19];
    const float* de_b1  = (const float*)d_in[20];
    const float* de_w2  = (const float*)d_in[21];
    const float* de_b2  = (const float*)d_in[22];

    int bsz = in_sizes[0] / (CH * LRAW);

    zero_stats_kernel<<<1, 128>>>();

    size_t smemA = (size_t)K1A_SMEMF * sizeof(float);
    cudaFuncSetAttribute((const void*)k1a_kernel,
                         cudaFuncAttributeMaxDynamicSharedMemorySize, (int)smemA);
    k1a_kernel<<<296, K1A_WARPS * 32, smemA>>>(eegf, fg_w1, fg_b1, fg_w2, fg_b2, bsz);

    size_t smemB = (size_t)K1B_SMEMF * sizeof(float);
    cudaFuncSetAttribute((const void*)k1b_kernel,
                         cudaFuncAttributeMaxDynamicSharedMemorySize, (int)smemB);
    k1b_kernel<<<296, K1B_WARPS * 32, smemB>>>(raw, enc_w1, enc_b1, bsz);

    k2_kernel<<<592, K2_WARPS * 32>>>(enc_w2, enc_b2, bn1_g, bn1_b, bsz);
    k3_kernel<<<592, K3_WPB * 32>>>(eps, mu_w, mu_b, lv_w, lv_b,
                                    de_w1, de_b1, de_w2, de_b2,
                                    bn2_g, bn2_b, (float*)d_out, bsz);
}